// round 16
// baseline (speedup 1.0000x reference)
#include <cuda_runtime.h>
#include <math.h>
#include <math_constants.h>

// Problem constants (fixed by the dataset)
#define BB 64
#define PP 8732
#define OO 50
#define CC 81

#define THR 128                        // k_fat threads per block
#define MCH 512                        // priors per match chunk (128 thr * 4)
#define RT 4                           // priors per thread
#define MMB ((PP + MCH - 1) / MCH)     // match chunks per batch = 18
#define NMATCH (BB * MMB)              // 1152 match blocks
#define NROWS (BB * PP)                // 558848 rows
#define NGRP (NROWS / 4)               // 139712 four-row groups (exact)
#define TG 8                           // groups per ticket (32 rows)
#define NTICKETS (NGRP / TG)           // 17464 (exact)
#define NBLK (11 * 148)                // one wave at 11 blocks/SM = 1628
#define CECH 1024                      // priors per ce chunk
#define CEMB ((PP + CECH - 1) / CECH)  // 9 ce chunks per batch

// ---------------- scratch (static device globals; zero-init at load, ---------
// ---------------- self-cleaned at the end of every run by k_topk) ------------
__device__ unsigned long long g_key[BB * OO];   // 0 == identity (iou=0)
__device__ int   g_cb  [BB * PP];               // per (b,prior): tgt*256 + truth
__device__ float g_lse [BB * PP];               // per (b,prior): logsumexp
__device__ float g_ce  [BB * PP];               // per (b,prior): mining CE
__device__ float g_posce[BB];
__device__ int   g_numpos[BB];
__device__ float g_lossl;
__device__ float g_lossc;
__device__ int   g_npos_tot;
__device__ int   g_done;
__device__ int   g_ticket;                      // LSE work queue

// ------------------------- helpers -------------------------------------------
__device__ __forceinline__ float blockReduceSumF(float v, float* sbuf) {
    int lane = threadIdx.x & 31, w = threadIdx.x >> 5;
    #pragma unroll
    for (int o = 16; o; o >>= 1) v += __shfl_xor_sync(0xFFFFFFFFu, v, o);
    if (lane == 0) sbuf[w] = v;
    __syncthreads();
    int nw = blockDim.x >> 5;
    v = (threadIdx.x < nw) ? sbuf[threadIdx.x] : 0.f;
    if (w == 0) {
        #pragma unroll
        for (int o = 16; o; o >>= 1) v += __shfl_xor_sync(0xFFFFFFFFu, v, o);
    }
    return v;  // valid on thread 0
}

__device__ __forceinline__ int blockReduceSumI(int v, int* sbuf) {
    int lane = threadIdx.x & 31, w = threadIdx.x >> 5;
    #pragma unroll
    for (int o = 16; o; o >>= 1) v += __shfl_xor_sync(0xFFFFFFFFu, v, o);
    if (lane == 0) sbuf[w] = v;
    __syncthreads();
    int nw = blockDim.x >> 5;
    v = (threadIdx.x < nw) ? sbuf[threadIdx.x] : 0;
    if (w == 0) {
        #pragma unroll
        for (int o = 16; o; o >>= 1) v += __shfl_xor_sync(0xFFFFFFFFu, v, o);
    }
    return v;
}

__device__ __forceinline__ float smoothl1(float d) {
    float a = fabsf(d);
    return (a < 1.f) ? 0.5f * d * d : a - 0.5f;
}

// positive-prior smooth-L1 contribution
__device__ __forceinline__ float pos_ll(int b, int p, int o,
                                        const float (*s_t)[5],
                                        const float* __restrict__ priors,
                                        const float* __restrict__ loc) {
    float m0 = s_t[o][0], m1 = s_t[o][1], m2 = s_t[o][2], m3 = s_t[o][3];
    float4 pr = ((const float4*)priors)[p];
    float cx = (m0 + m2) * 0.5f;
    float cy = (m1 + m3) * 0.5f;
    float gx = (cx - pr.x) / (0.1f * pr.z);
    float gy = (cy - pr.y) / (0.1f * pr.w);
    float gwv = logf((m2 - m0) / pr.z) * 5.f;
    float ghv = logf((m3 - m1) / pr.w) * 5.f;
    float4 lv = *((const float4*)(loc + (size_t)(b * PP + p) * 4));
    return smoothl1(lv.x - gx) + smoothl1(lv.y - gy) +
           smoothl1(lv.z - gwv) + smoothl1(lv.w - ghv);
}

// pack iou with 2-bit slot id in low mantissa bits (3-j: smaller j wins ties)
__device__ __forceinline__ float pack_key(float iou, int j) {
    unsigned u = (__float_as_uint(iou) & ~3u) | (unsigned)(3 - j);
    return __uint_as_float(u);
}

// ---- K1: one-wave fat kernel: match chunks + ticket-queue logsumexp ---------
// 1152 match blocks (128 thr, 512-prior chunks; join LSE queue when done) +
// 476 pure-LSE blocks. 11 blocks/SM x 4 warps = 44 warps/SM.
__global__ void __launch_bounds__(THR, 11) k_fat(const float* __restrict__ targets,
                                                 const float* __restrict__ priors,
                                                 const float* __restrict__ conf) {
    int tid = threadIdx.x;
    if (blockIdx.x < NMATCH) {
        // ================= matching =================
        int b  = blockIdx.x / MMB;
        int p0 = (blockIdx.x % MMB) * MCH;
        __shared__ float4 s_t4[OO];
        __shared__ float2 s_meta[OO];               // (area, label)
        __shared__ unsigned long long s_key[OO];

        for (int i = tid; i < OO; i += THR) {
            const float* tr = targets + (size_t)(b * OO + i) * 5;
            float x0 = tr[0], y0 = tr[1], x1 = tr[2], y1 = tr[3];
            s_t4[i] = make_float4(x0, y0, x1, y1);
            s_meta[i] = make_float2((x1 - x0) * (y1 - y0), tr[4]);
            s_key[i]  = 0ull;                       // identity: iou = 0
        }
        __syncthreads();

        int pbase = p0 + tid;
        float bx0[RT], by0[RT], bx1[RT], by1[RT], ab[RT];
        float bi[RT]; int bo[RT];
        #pragma unroll
        for (int j = 0; j < RT; j++) {
            int p = pbase + j * THR;
            if (p < PP) {
                float4 pr = ((const float4*)priors)[p];
                float hx = pr.z * 0.5f, hy = pr.w * 0.5f;
                bx0[j] = pr.x - hx; by0[j] = pr.y - hy;
                bx1[j] = pr.x + hx; by1[j] = pr.y + hy;
                ab[j]  = (bx1[j] - bx0[j]) * (by1[j] - by0[j]);
            } else {   // degenerate: never intersects; uni = truth area > 0
                bx0[j] = 4.f; by0[j] = 4.f; bx1[j] = 3.f; by1[j] = 3.f; ab[j] = 0.f;
            }
            bi[j] = 0.f; bo[j] = 0;     // iou=0 baseline, first index wins ties
        }

        for (int o = 0; o < OO; o++) {
            float4 t = s_t4[o];
            float area = s_meta[o].x;
            float curkey = __uint_as_float((unsigned)(s_key[o] >> 32)); // racy ok
            float ck = 0.f;                         // packed candidate key
            #pragma unroll
            for (int j = 0; j < RT; j++) {
                float lx = fmaxf(t.x, bx0[j]), ly = fmaxf(t.y, by0[j]);
                float rx = fminf(t.z, bx1[j]), ry = fminf(t.w, by1[j]);
                float w = fmaxf(rx - lx, 0.f);
                float h = fmaxf(ry - ly, 0.f);
                float inter = w * h;
                float uni   = area + ab[j] - inter;
                float iou   = __fdividef(inter, uni);     // MUFU.RCP + FMUL
                // per-prior argmax over truths (strict >, earlier o wins ties)
                if (iou > bi[j]) { bi[j] = iou; bo[j] = o; }
                // per-truth candidate: packed (iou | 3-j) so one FMNMX suffices
                ck = fmaxf(ck, pack_key(iou, j));
            }
            // pass iff this thread's candidate beats the (racy) current key
            if (__ballot_sync(0xFFFFFFFFu, ck > curkey)) {
                int cp = pbase + (3 - (__float_as_uint(ck) & 3u)) * THR;
                float ci = ck;
                #pragma unroll
                for (int off = 16; off; off >>= 1) {
                    float oi = __shfl_down_sync(0xFFFFFFFFu, ci, off);
                    int   op = __shfl_down_sync(0xFFFFFFFFu, cp, off);
                    bool take = (oi > ci) || (oi == ci && op < cp);
                    if (take) { ci = oi; cp = op; }
                }
                if ((tid & 31) == 0) {
                    unsigned long long nk =
                        ((unsigned long long)__float_as_uint(ci) << 32) |
                        (unsigned long long)(0xFFFFFFFFu - (unsigned)cp);
                    atomicMax(&s_key[o], nk);
                }
            }
        }
        #pragma unroll
        for (int j = 0; j < RT; j++) {
            int p = pbase + j * THR;
            if (p < PP) {
                int c = (bi[j] < 0.5f) ? 0 : ((int)s_meta[bo[j]].y + 1);
                g_cb[b * PP + p] = c * 256 + bo[j];
            }
        }
        __syncthreads();
        for (int o = tid; o < OO; o += THR)
            atomicMax(&g_key[b * OO + o], s_key[o]);
    }

    // ========== logsumexp: persistent warps pulling tickets (32 rows each) ====
    int lane = tid & 31;
    bool tail = (lane < CC - 64);              // lane < 17
    bool lo   = (lane < 16);
    for (;;) {
        int t;
        if (lane == 0) t = atomicAdd(&g_ticket, 1);
        t = __shfl_sync(0xFFFFFFFFu, t, 0);
        if (t >= NTICKETS) break;
        int g0 = t * TG;
        #pragma unroll 2
        for (int g = g0; g < g0 + TG; g++) {
            int row0 = g * 4;
            const float* base = conf + (size_t)row0 * CC;
            float a0 = base[lane],            a1 = base[lane + 32];
            float b0 = base[CC + lane],       b1 = base[CC + lane + 32];
            float c0 = base[2 * CC + lane],   c1 = base[2 * CC + lane + 32];
            float d0 = base[3 * CC + lane],   d1 = base[3 * CC + lane + 32];
            float a2 = tail ? base[lane + 64] : 0.f;
            float b2 = tail ? base[CC + lane + 64] : 0.f;
            float c2 = tail ? base[2 * CC + lane + 64] : 0.f;
            float d2 = tail ? base[3 * CC + lane + 64] : 0.f;

            float sa = __expf(a0) + __expf(a1) + (tail ? __expf(a2) : 0.f);
            float sb = __expf(b0) + __expf(b1) + (tail ? __expf(b2) : 0.f);
            float sc = __expf(c0) + __expf(c1) + (tail ? __expf(c2) : 0.f);
            float sd = __expf(d0) + __expf(d1) + (tail ? __expf(d2) : 0.f);

            // 2-phase multi-value reduction: fold rows across half-warps first
            float t0 = __shfl_xor_sync(0xFFFFFFFFu, sa, 16);
            float t1 = __shfl_xor_sync(0xFFFFFFFFu, sb, 16);
            float t2 = __shfl_xor_sync(0xFFFFFFFFu, sc, 16);
            float t3 = __shfl_xor_sync(0xFFFFFFFFu, sd, 16);
            float x = lo ? (sa + t0) : (sc + t2);   // row0 | row2 partials
            float y = lo ? (sb + t1) : (sd + t3);   // row1 | row3 partials
            #pragma unroll
            for (int o = 8; o; o >>= 1) {
                x += __shfl_xor_sync(0xFFFFFFFFu, x, o);
                y += __shfl_xor_sync(0xFFFFFFFFu, y, o);
            }
            // lane 0: (row0,row1) totals; lane 16: (row2,row3) totals
            if ((lane & 15) == 0) {
                float2 r = make_float2(__logf(x), __logf(y));
                *(float2*)(g_lse + row0 + (lo ? 0 : 2)) = r;
            }
        }
    }
}

// ---- K2: CE + in-block override + smooth-L1 + counters ----------------------
// 4 priors per thread: one LDG.128 of g_cb feeds 4 INDEPENDENT scattered conf
// loads (MLP=4 on the cb->conf dependency chain).
__global__ void __launch_bounds__(256, 4) k_ce(const float* __restrict__ conf,
                                               const float* __restrict__ targets,
                                               const float* __restrict__ priors,
                                               const float* __restrict__ loc) {
    int b = blockIdx.y, tid = threadIdx.x;
    int p0 = blockIdx.x * CECH;
    __shared__ float s_t[OO][5];
    __shared__ __align__(16) int s_ov[CECH];
    __shared__ float sbufF[32];
    __shared__ int   sbufI[32];

    #pragma unroll
    for (int i = tid; i < CECH; i += 256) s_ov[i] = -1;
    for (int i = tid; i < OO * 5; i += 256)
        ((float*)s_t)[i] = targets[(size_t)b * OO * 5 + i];
    __syncthreads();
    // decode per-truth best priors; last-wins scatter == max-truth-index wins
    if (tid < OO) {
        unsigned long long k = g_key[b * OO + tid];
        int tp = (int)(0xFFFFFFFFu - (unsigned)(k & 0xFFFFFFFFull));
        int rel = tp - p0;
        if (rel >= 0 && rel < CECH) atomicMax(&s_ov[rel], tid);
    }
    __syncthreads();

    int p = p0 + tid * 4;                       // PP % 4 == 0 -> full or skip
    int np = 0; float posce = 0.f, ll = 0.f;
    if (p < PP) {
        int idx = b * PP + p;
        int4 cb4 = *(const int4*)(g_cb + idx);
        int4 ov4 = *(const int4*)(s_ov + tid * 4);
        float4 lse4 = *(const float4*)(g_lse + idx);

        int tgt0 = (ov4.x >= 0) ? (int)s_t[ov4.x][4] + 1 : (cb4.x >> 8);
        int o0   = (ov4.x >= 0) ? ov4.x : (cb4.x & 255);
        int tgt1 = (ov4.y >= 0) ? (int)s_t[ov4.y][4] + 1 : (cb4.y >> 8);
        int o1   = (ov4.y >= 0) ? ov4.y : (cb4.y & 255);
        int tgt2 = (ov4.z >= 0) ? (int)s_t[ov4.z][4] + 1 : (cb4.z >> 8);
        int o2   = (ov4.z >= 0) ? ov4.z : (cb4.z & 255);
        int tgt3 = (ov4.w >= 0) ? (int)s_t[ov4.w][4] + 1 : (cb4.w >> 8);
        int o3   = (ov4.w >= 0) ? ov4.w : (cb4.w & 255);

        // 4 independent scattered loads
        float v0 = conf[(size_t)(idx + 0) * CC + tgt0];
        float v1 = conf[(size_t)(idx + 1) * CC + tgt1];
        float v2 = conf[(size_t)(idx + 2) * CC + tgt2];
        float v3 = conf[(size_t)(idx + 3) * CC + tgt3];

        float4 w4;
        float ce0 = lse4.x - v0, ce1 = lse4.y - v1;
        float ce2 = lse4.z - v2, ce3 = lse4.w - v3;
        w4.x = ce0; w4.y = ce1; w4.z = ce2; w4.w = ce3;
        if (tgt0 > 0) { np++; posce += ce0; w4.x = 0.f;
                        ll += pos_ll(b, p + 0, o0, s_t, priors, loc); }
        if (tgt1 > 0) { np++; posce += ce1; w4.y = 0.f;
                        ll += pos_ll(b, p + 1, o1, s_t, priors, loc); }
        if (tgt2 > 0) { np++; posce += ce2; w4.z = 0.f;
                        ll += pos_ll(b, p + 2, o2, s_t, priors, loc); }
        if (tgt3 > 0) { np++; posce += ce3; w4.w = 0.f;
                        ll += pos_ll(b, p + 3, o3, s_t, priors, loc); }
        *(float4*)(g_ce + idx) = w4;
    }
    int npT = blockReduceSumI(np, sbufI);
    __syncthreads();
    float pcT = blockReduceSumF(posce, sbufF);
    __syncthreads();
    float llT = blockReduceSumF(ll, sbufF);
    if (tid == 0) {
        if (npT) { atomicAdd(&g_numpos[b], npT); atomicAdd(&g_npos_tot, npT); }
        atomicAdd(&g_posce[b], pcT);
        atomicAdd(&g_lossl, llT);
    }
}

// ---- K3: per-batch radix top-k + conf loss + finalize + state reset ---------
__global__ void k_topk(float* __restrict__ out) {
    int b = blockIdx.x, tid = threadIdx.x;
    __shared__ float s_ce[PP];                 // 34928 B
    __shared__ unsigned int hist[256];
    __shared__ unsigned int sh_prefix;
    __shared__ int sh_rem;
    __shared__ float sbufF[32];

    const float4* ce4 = (const float4*)(g_ce + (size_t)b * PP);
    float4* s4 = (float4*)s_ce;
    for (int p = tid; p < PP / 4; p += 1024) s4[p] = ce4[p];   // PP = 2183*4

    int np = g_numpos[b];
    int k = min(3 * np, PP - 1);
    float contrib = g_posce[b];

    if (k > 0) {
        if (tid == 0) { sh_prefix = 0u; sh_rem = k; }
        __syncthreads();
        // exact radix select of k-th largest (ce >= 0 so uint order == float)
        for (int pass = 0; pass < 4; pass++) {
            int shift = 24 - 8 * pass;
            if (tid < 256) hist[tid] = 0u;
            __syncthreads();
            unsigned pfx = sh_prefix;
            for (int p = tid; p < PP; p += 1024) {
                unsigned key = __float_as_uint(s_ce[p]);
                bool ok = (pass == 0) ||
                          ((key >> (shift + 8)) == (pfx >> (shift + 8)));
                if (ok) atomicAdd(&hist[(key >> shift) & 255u], 1u);
            }
            __syncthreads();
            if (tid == 0) {
                int rem = sh_rem;
                int d = 255;
                for (; d > 0; d--) {
                    int c = (int)hist[d];
                    if (rem <= c) break;
                    rem -= c;
                }
                sh_prefix = pfx | ((unsigned)d << shift);
                sh_rem = rem;
            }
            __syncthreads();
        }
        unsigned T = sh_prefix;
        float tv = __uint_as_float(T);
        float sum = 0.f;
        for (int p = tid; p < PP; p += 1024) {
            float v = s_ce[p];
            if (__float_as_uint(v) > T) sum += v;
        }
        float sumT = blockReduceSumF(sum, sbufF);
        if (tid == 0) contrib += sumT + tv * (float)sh_rem;
    }

    __syncthreads();                 // everyone done reading per-batch state
    // per-batch state reset for the next graph replay
    if (tid < OO) g_key[b * OO + tid] = 0ull;
    if (tid == 64) { g_numpos[b] = 0; g_posce[b] = 0.f; }

    if (tid == 0) {
        atomicAdd(&g_lossc, contrib);
        __threadfence();
        int t = atomicAdd(&g_done, 1);
        if (t == BB - 1) {           // all contributions visible
            float N = (float)g_npos_tot;
            out[0] = g_lossl / N;
            out[1] = g_lossc / N;
            // global state reset for the next graph replay
            g_lossl = 0.f; g_lossc = 0.f; g_npos_tot = 0; g_done = 0;
            g_ticket = 0;
        }
    }
}

// ------------------------- launch --------------------------------------------
extern "C" void kernel_launch(void* const* d_in, const int* in_sizes, int n_in,
                              void* d_out, int out_size) {
    const float* loc     = (const float*)d_in[0];
    const float* conf    = (const float*)d_in[1];
    const float* targets = (const float*)d_in[2];
    const float* priors  = (const float*)d_in[3];
    float* out = (float*)d_out;

    k_fat<<<NBLK, THR>>>(targets, priors, conf);

    dim3 gce(CEMB, BB);
    k_ce<<<gce, 256>>>(conf, targets, priors, loc);

    k_topk<<<BB, 1024>>>(out);
}

// round 17
// speedup vs baseline: 1.1648x; 1.1648x over previous
#include <cuda_runtime.h>
#include <math.h>
#include <math_constants.h>

// Problem constants (fixed by the dataset)
#define BB 64
#define PP 8732
#define OO 50
#define CC 81

#define CH 1024                        // priors per match/ce chunk
#define RT 4                           // priors per thread (256 thr * 4 = 1024)
#define MB ((PP + CH - 1) / CH)        // chunks per batch = 9
#define NMATCH (BB * MB)               // 576 match blocks
#define NROWS (BB * PP)                // 558848 rows
#define NGRP (NROWS / 4)               // 139712 four-row groups (exact)
#define TG 8                           // groups per ticket (32 rows)
#define NTICKETS (NGRP / TG)           // 17464 (exact)
#define NBLK (5 * 148)                 // one wave at 5 blocks/SM = 740

// ---------------- scratch (static device globals; zero-init at load, ---------
// ---------------- self-cleaned at the end of every run by k_topk) ------------
__device__ unsigned long long g_key[BB * OO];   // 0 == identity (iou=0)
__device__ int   g_cb  [BB * PP];               // per (b,prior): tgt*256 + truth
__device__ float g_lse [BB * PP];               // per (b,prior): logsumexp
__device__ float g_ce  [BB * PP];               // per (b,prior): mining CE
__device__ float g_posce[BB];
__device__ int   g_numpos[BB];
__device__ float g_lossl;
__device__ float g_lossc;
__device__ int   g_npos_tot;
__device__ int   g_done;
__device__ int   g_ticket;                      // LSE work queue

// ------------------------- helpers -------------------------------------------
__device__ __forceinline__ float blockReduceSumF(float v, float* sbuf) {
    int lane = threadIdx.x & 31, w = threadIdx.x >> 5;
    #pragma unroll
    for (int o = 16; o; o >>= 1) v += __shfl_xor_sync(0xFFFFFFFFu, v, o);
    if (lane == 0) sbuf[w] = v;
    __syncthreads();
    int nw = blockDim.x >> 5;
    v = (threadIdx.x < nw) ? sbuf[threadIdx.x] : 0.f;
    if (w == 0) {
        #pragma unroll
        for (int o = 16; o; o >>= 1) v += __shfl_xor_sync(0xFFFFFFFFu, v, o);
    }
    return v;  // valid on thread 0
}

__device__ __forceinline__ int blockReduceSumI(int v, int* sbuf) {
    int lane = threadIdx.x & 31, w = threadIdx.x >> 5;
    #pragma unroll
    for (int o = 16; o; o >>= 1) v += __shfl_xor_sync(0xFFFFFFFFu, v, o);
    if (lane == 0) sbuf[w] = v;
    __syncthreads();
    int nw = blockDim.x >> 5;
    v = (threadIdx.x < nw) ? sbuf[threadIdx.x] : 0;
    if (w == 0) {
        #pragma unroll
        for (int o = 16; o; o >>= 1) v += __shfl_xor_sync(0xFFFFFFFFu, v, o);
    }
    return v;
}

__device__ __forceinline__ float smoothl1(float d) {
    float a = fabsf(d);
    return (a < 1.f) ? 0.5f * d * d : a - 0.5f;
}

// positive-prior smooth-L1 contribution
__device__ __forceinline__ float pos_ll(int b, int p, int o,
                                        const float (*s_t)[5],
                                        const float* __restrict__ priors,
                                        const float* __restrict__ loc) {
    float m0 = s_t[o][0], m1 = s_t[o][1], m2 = s_t[o][2], m3 = s_t[o][3];
    float4 pr = ((const float4*)priors)[p];
    float cx = (m0 + m2) * 0.5f;
    float cy = (m1 + m3) * 0.5f;
    float gx = (cx - pr.x) / (0.1f * pr.z);
    float gy = (cy - pr.y) / (0.1f * pr.w);
    float gwv = logf((m2 - m0) / pr.z) * 5.f;
    float ghv = logf((m3 - m1) / pr.w) * 5.f;
    float4 lv = *((const float4*)(loc + (size_t)(b * PP + p) * 4));
    return smoothl1(lv.x - gx) + smoothl1(lv.y - gy) +
           smoothl1(lv.z - gwv) + smoothl1(lv.w - ghv);
}

// pack iou with 2-bit slot id in low mantissa bits (3-j: smaller j wins ties)
__device__ __forceinline__ float pack_key(float iou, int j) {
    unsigned u = (__float_as_uint(iou) & ~3u) | (unsigned)(3 - j);
    return __uint_as_float(u);
}

// ---- K1: one-wave fat kernel: match chunks + ticket-queue logsumexp ---------
// 576 match blocks (join LSE queue when done) + 164 pure-LSE blocks that
// chew DRAM-bound tickets concurrently with the ALU-bound match phase.
__global__ void __launch_bounds__(256, 5) k_fat(const float* __restrict__ targets,
                                                const float* __restrict__ priors,
                                                const float* __restrict__ conf) {
    int tid = threadIdx.x;
    if (blockIdx.x < NMATCH) {
        // ================= matching =================
        int b  = blockIdx.x / MB;
        int p0 = (blockIdx.x % MB) * CH;
        __shared__ float4 s_t4[OO];
        __shared__ float2 s_meta[OO];               // (area, label)
        __shared__ unsigned long long s_key[OO];

        for (int i = tid; i < OO; i += 256) {
            const float* tr = targets + (size_t)(b * OO + i) * 5;
            float x0 = tr[0], y0 = tr[1], x1 = tr[2], y1 = tr[3];
            s_t4[i] = make_float4(x0, y0, x1, y1);
            s_meta[i] = make_float2((x1 - x0) * (y1 - y0), tr[4]);
            s_key[i]  = 0ull;                       // identity: iou = 0
        }
        __syncthreads();

        int pbase = p0 + tid;
        float bx0[RT], by0[RT], bx1[RT], by1[RT], ab[RT];
        float bi[RT]; int bo[RT];
        #pragma unroll
        for (int j = 0; j < RT; j++) {
            int p = pbase + j * 256;
            if (p < PP) {
                float4 pr = ((const float4*)priors)[p];
                float hx = pr.z * 0.5f, hy = pr.w * 0.5f;
                bx0[j] = pr.x - hx; by0[j] = pr.y - hy;
                bx1[j] = pr.x + hx; by1[j] = pr.y + hy;
                ab[j]  = (bx1[j] - bx0[j]) * (by1[j] - by0[j]);
            } else {   // degenerate: never intersects; uni = truth area > 0
                bx0[j] = 4.f; by0[j] = 4.f; bx1[j] = 3.f; by1[j] = 3.f; ab[j] = 0.f;
            }
            bi[j] = 0.f; bo[j] = 0;     // iou=0 baseline, first index wins ties
        }

        for (int o = 0; o < OO; o++) {
            float4 t = s_t4[o];
            float area = s_meta[o].x;
            unsigned curk = (unsigned)(s_key[o] >> 32);     // racy read: ok
            float ck = 0.f;                                 // packed candidate
            #pragma unroll
            for (int j = 0; j < RT; j++) {
                float lx = fmaxf(t.x, bx0[j]), ly = fmaxf(t.y, by0[j]);
                float rx = fminf(t.z, bx1[j]), ry = fminf(t.w, by1[j]);
                float w = fmaxf(rx - lx, 0.f);
                float h = fmaxf(ry - ly, 0.f);
                float inter = w * h;
                float uni   = area + ab[j] - inter;
                float iou   = __fdividef(inter, uni);     // MUFU.RCP + FMUL
                // per-prior argmax over truths (strict >, earlier o wins ties)
                if (iou > bi[j]) { bi[j] = iou; bo[j] = o; }
                // per-truth candidate: packed (iou | 3-j), one FMNMX
                ck = fmaxf(ck, pack_key(iou, j));
            }
            // single-instruction warp max (uint order == float order, ck >= 0)
            unsigned mk = __float_as_uint(ck);
            unsigned wmax = __reduce_max_sync(0xFFFFFFFFu, mk);
            if (wmax > curk) {
                // leader = lowest lane holding the max -> smallest prior index
                unsigned ball = __ballot_sync(0xFFFFFFFFu, mk == wmax);
                if ((tid & 31) == (__ffs(ball) - 1)) {
                    int cp = pbase + (3 - (int)(mk & 3u)) * 256;
                    unsigned long long nk =
                        ((unsigned long long)wmax << 32) |
                        (unsigned long long)(0xFFFFFFFFu - (unsigned)cp);
                    atomicMax(&s_key[o], nk);
                }
            }
        }
        #pragma unroll
        for (int j = 0; j < RT; j++) {
            int p = pbase + j * 256;
            if (p < PP) {
                int c = (bi[j] < 0.5f) ? 0 : ((int)s_meta[bo[j]].y + 1);
                g_cb[b * PP + p] = c * 256 + bo[j];
            }
        }
        __syncthreads();
        for (int o = tid; o < OO; o += 256)
            atomicMax(&g_key[b * OO + o], s_key[o]);
    }

    // ========== logsumexp: persistent warps pulling tickets (32 rows each) ====
    int lane = tid & 31;
    bool tail = (lane < CC - 64);              // lane < 17
    bool lo   = (lane < 16);
    for (;;) {
        int t;
        if (lane == 0) t = atomicAdd(&g_ticket, 1);
        t = __shfl_sync(0xFFFFFFFFu, t, 0);
        if (t >= NTICKETS) break;
        int g0 = t * TG;
        #pragma unroll 2
        for (int g = g0; g < g0 + TG; g++) {
            int row0 = g * 4;
            const float* base = conf + (size_t)row0 * CC;
            float a0 = base[lane],            a1 = base[lane + 32];
            float b0 = base[CC + lane],       b1 = base[CC + lane + 32];
            float c0 = base[2 * CC + lane],   c1 = base[2 * CC + lane + 32];
            float d0 = base[3 * CC + lane],   d1 = base[3 * CC + lane + 32];
            float a2 = tail ? base[lane + 64] : 0.f;
            float b2 = tail ? base[CC + lane + 64] : 0.f;
            float c2 = tail ? base[2 * CC + lane + 64] : 0.f;
            float d2 = tail ? base[3 * CC + lane + 64] : 0.f;

            float sa = __expf(a0) + __expf(a1) + (tail ? __expf(a2) : 0.f);
            float sb = __expf(b0) + __expf(b1) + (tail ? __expf(b2) : 0.f);
            float sc = __expf(c0) + __expf(c1) + (tail ? __expf(c2) : 0.f);
            float sd = __expf(d0) + __expf(d1) + (tail ? __expf(d2) : 0.f);

            // 2-phase multi-value reduction: fold rows across half-warps first
            float t0 = __shfl_xor_sync(0xFFFFFFFFu, sa, 16);
            float t1 = __shfl_xor_sync(0xFFFFFFFFu, sb, 16);
            float t2 = __shfl_xor_sync(0xFFFFFFFFu, sc, 16);
            float t3 = __shfl_xor_sync(0xFFFFFFFFu, sd, 16);
            float x = lo ? (sa + t0) : (sc + t2);   // row0 | row2 partials
            float y = lo ? (sb + t1) : (sd + t3);   // row1 | row3 partials
            #pragma unroll
            for (int o = 8; o; o >>= 1) {
                x += __shfl_xor_sync(0xFFFFFFFFu, x, o);
                y += __shfl_xor_sync(0xFFFFFFFFu, y, o);
            }
            // lane 0: (row0,row1) totals; lane 16: (row2,row3) totals
            if ((lane & 15) == 0) {
                float2 r = make_float2(__logf(x), __logf(y));
                *(float2*)(g_lse + row0 + (lo ? 0 : 2)) = r;
            }
        }
    }
}

// ---- K2: CE + in-block override + smooth-L1 + counters ----------------------
// 4 priors per thread: one LDG.128 of g_cb feeds 4 INDEPENDENT scattered conf
// loads (MLP=4 on the cb->conf dependency chain).
__global__ void __launch_bounds__(256, 4) k_ce(const float* __restrict__ conf,
                                               const float* __restrict__ targets,
                                               const float* __restrict__ priors,
                                               const float* __restrict__ loc) {
    int b = blockIdx.y, tid = threadIdx.x;
    int p0 = blockIdx.x * CH;
    __shared__ float s_t[OO][5];
    __shared__ __align__(16) int s_ov[CH];
    __shared__ float sbufF[32];
    __shared__ int   sbufI[32];

    #pragma unroll
    for (int i = tid; i < CH; i += 256) s_ov[i] = -1;
    for (int i = tid; i < OO * 5; i += 256)
        ((float*)s_t)[i] = targets[(size_t)b * OO * 5 + i];
    __syncthreads();
    // decode per-truth best priors; last-wins scatter == max-truth-index wins
    if (tid < OO) {
        unsigned long long k = g_key[b * OO + tid];
        int tp = (int)(0xFFFFFFFFu - (unsigned)(k & 0xFFFFFFFFull));
        int rel = tp - p0;
        if (rel >= 0 && rel < CH) atomicMax(&s_ov[rel], tid);
    }
    __syncthreads();

    int p = p0 + tid * 4;                       // PP % 4 == 0 -> full or skip
    int np = 0; float posce = 0.f, ll = 0.f;
    if (p < PP) {
        int idx = b * PP + p;
        int4 cb4 = *(const int4*)(g_cb + idx);
        int4 ov4 = *(const int4*)(s_ov + tid * 4);
        float4 lse4 = *(const float4*)(g_lse + idx);

        int tgt0 = (ov4.x >= 0) ? (int)s_t[ov4.x][4] + 1 : (cb4.x >> 8);
        int o0   = (ov4.x >= 0) ? ov4.x : (cb4.x & 255);
        int tgt1 = (ov4.y >= 0) ? (int)s_t[ov4.y][4] + 1 : (cb4.y >> 8);
        int o1   = (ov4.y >= 0) ? ov4.y : (cb4.y & 255);
        int tgt2 = (ov4.z >= 0) ? (int)s_t[ov4.z][4] + 1 : (cb4.z >> 8);
        int o2   = (ov4.z >= 0) ? ov4.z : (cb4.z & 255);
        int tgt3 = (ov4.w >= 0) ? (int)s_t[ov4.w][4] + 1 : (cb4.w >> 8);
        int o3   = (ov4.w >= 0) ? ov4.w : (cb4.w & 255);

        // 4 independent scattered loads
        float v0 = conf[(size_t)(idx + 0) * CC + tgt0];
        float v1 = conf[(size_t)(idx + 1) * CC + tgt1];
        float v2 = conf[(size_t)(idx + 2) * CC + tgt2];
        float v3 = conf[(size_t)(idx + 3) * CC + tgt3];

        float4 w4;
        float ce0 = lse4.x - v0, ce1 = lse4.y - v1;
        float ce2 = lse4.z - v2, ce3 = lse4.w - v3;
        w4.x = ce0; w4.y = ce1; w4.z = ce2; w4.w = ce3;
        if (tgt0 > 0) { np++; posce += ce0; w4.x = 0.f;
                        ll += pos_ll(b, p + 0, o0, s_t, priors, loc); }
        if (tgt1 > 0) { np++; posce += ce1; w4.y = 0.f;
                        ll += pos_ll(b, p + 1, o1, s_t, priors, loc); }
        if (tgt2 > 0) { np++; posce += ce2; w4.z = 0.f;
                        ll += pos_ll(b, p + 2, o2, s_t, priors, loc); }
        if (tgt3 > 0) { np++; posce += ce3; w4.w = 0.f;
                        ll += pos_ll(b, p + 3, o3, s_t, priors, loc); }
        *(float4*)(g_ce + idx) = w4;
    }
    int npT = blockReduceSumI(np, sbufI);
    __syncthreads();
    float pcT = blockReduceSumF(posce, sbufF);
    __syncthreads();
    float llT = blockReduceSumF(ll, sbufF);
    if (tid == 0) {
        if (npT) { atomicAdd(&g_numpos[b], npT); atomicAdd(&g_npos_tot, npT); }
        atomicAdd(&g_posce[b], pcT);
        atomicAdd(&g_lossl, llT);
    }
}

// ---- K3: per-batch radix top-k + conf loss + finalize + state reset ---------
__global__ void k_topk(float* __restrict__ out) {
    int b = blockIdx.x, tid = threadIdx.x;
    __shared__ float s_ce[PP];                 // 34928 B
    __shared__ unsigned int hist[256];
    __shared__ unsigned int sh_prefix;
    __shared__ int sh_rem;
    __shared__ float sbufF[32];

    const float4* ce4 = (const float4*)(g_ce + (size_t)b * PP);
    float4* s4 = (float4*)s_ce;
    for (int p = tid; p < PP / 4; p += 1024) s4[p] = ce4[p];   // PP = 2183*4

    int np = g_numpos[b];
    int k = min(3 * np, PP - 1);
    float contrib = g_posce[b];

    if (k > 0) {
        if (tid == 0) { sh_prefix = 0u; sh_rem = k; }
        __syncthreads();
        // exact radix select of k-th largest (ce >= 0 so uint order == float)
        for (int pass = 0; pass < 4; pass++) {
            int shift = 24 - 8 * pass;
            if (tid < 256) hist[tid] = 0u;
            __syncthreads();
            unsigned pfx = sh_prefix;
            for (int p = tid; p < PP; p += 1024) {
                unsigned key = __float_as_uint(s_ce[p]);
                bool ok = (pass == 0) ||
                          ((key >> (shift + 8)) == (pfx >> (shift + 8)));
                if (ok) atomicAdd(&hist[(key >> shift) & 255u], 1u);
            }
            __syncthreads();
            if (tid == 0) {
                int rem = sh_rem;
                int d = 255;
                for (; d > 0; d--) {
                    int c = (int)hist[d];
                    if (rem <= c) break;
                    rem -= c;
                }
                sh_prefix = pfx | ((unsigned)d << shift);
                sh_rem = rem;
            }
            __syncthreads();
        }
        unsigned T = sh_prefix;
        float tv = __uint_as_float(T);
        float sum = 0.f;
        for (int p = tid; p < PP; p += 1024) {
            float v = s_ce[p];
            if (__float_as_uint(v) > T) sum += v;
        }
        float sumT = blockReduceSumF(sum, sbufF);
        if (tid == 0) contrib += sumT + tv * (float)sh_rem;
    }

    __syncthreads();                 // everyone done reading per-batch state
    // per-batch state reset for the next graph replay
    if (tid < OO) g_key[b * OO + tid] = 0ull;
    if (tid == 64) { g_numpos[b] = 0; g_posce[b] = 0.f; }

    if (tid == 0) {
        atomicAdd(&g_lossc, contrib);
        __threadfence();
        int t = atomicAdd(&g_done, 1);
        if (t == BB - 1) {           // all contributions visible
            float N = (float)g_npos_tot;
            out[0] = g_lossl / N;
            out[1] = g_lossc / N;
            // global state reset for the next graph replay
            g_lossl = 0.f; g_lossc = 0.f; g_npos_tot = 0; g_done = 0;
            g_ticket = 0;
        }
    }
}

// ------------------------- launch --------------------------------------------
extern "C" void kernel_launch(void* const* d_in, const int* in_sizes, int n_in,
                              void* d_out, int out_size) {
    const float* loc     = (const float*)d_in[0];
    const float* conf    = (const float*)d_in[1];
    const float* targets = (const float*)d_in[2];
    const float* priors  = (const float*)d_in[3];
    float* out = (float*)d_out;

    k_fat<<<NBLK, 256>>>(targets, priors, conf);

    dim3 gce(MB, BB);
    k_ce<<<gce, 256>>>(conf, targets, priors, loc);

    k_topk<<<BB, 1024>>>(out);
}